// round 15
// baseline (speedup 1.0000x reference)
#include <cuda_runtime.h>
#include <cuda_fp16.h>
#include <cstdint>

// Problem constants
#define Bb    2
#define Sq    2048
#define DIN   2048
#define DOUT  2048
#define NH    16
#define NKV   4
#define HD    128
#define MROWS (Bb*Sq)        // 4096
#define DKV   (NKV*HD)       // 512
#define NQKV  (DOUT + 2*DKV) // 3072

// Scratch
__device__ __half g_xh[(size_t)MROWS*DIN];
__device__ __half g_wqkv[(size_t)DIN*NQKV];   // Wq,Wk rope-pair permuted; Wv plain
__device__ __half g_woh[(size_t)DOUT*DOUT];
__device__ __half g_qh[(size_t)MROWS*DOUT];   // permuted d, rope applied, scaled by log2e/sqrt(HD)
__device__ __half g_kh[(size_t)MROWS*DKV];    // permuted d, rope applied
__device__ __half g_vh[(size_t)MROWS*DKV];
__device__ __half g_ch[(size_t)MROWS*DOUT];

// ---------------------------------------------------------------------------
// Helpers
// ---------------------------------------------------------------------------
__device__ __forceinline__ uint32_t smem_u32(const void* p) {
    uint32_t a;
    asm("{ .reg .u64 t; cvta.to.shared.u64 t, %1; cvt.u32.u64 %0, t; }" : "=r"(a) : "l"(p));
    return a;
}
__device__ __forceinline__ void ldsm_x4(uint32_t& r0, uint32_t& r1, uint32_t& r2, uint32_t& r3,
                                        uint32_t addr) {
    asm volatile("ldmatrix.sync.aligned.m8n8.x4.shared.b16 {%0,%1,%2,%3}, [%4];"
                 : "=r"(r0), "=r"(r1), "=r"(r2), "=r"(r3) : "r"(addr));
}
__device__ __forceinline__ void ldsm_x4t(uint32_t& r0, uint32_t& r1, uint32_t& r2, uint32_t& r3,
                                         uint32_t addr) {
    asm volatile("ldmatrix.sync.aligned.m8n8.x4.trans.shared.b16 {%0,%1,%2,%3}, [%4];"
                 : "=r"(r0), "=r"(r1), "=r"(r2), "=r"(r3) : "r"(addr));
}
__device__ __forceinline__ void mma16816(float* d, const uint32_t* a, const uint32_t* b) {
    asm volatile(
        "mma.sync.aligned.m16n8k16.row.col.f32.f16.f16.f32 "
        "{%0,%1,%2,%3}, {%4,%5,%6,%7}, {%8,%9}, {%0,%1,%2,%3};"
        : "+f"(d[0]), "+f"(d[1]), "+f"(d[2]), "+f"(d[3])
        : "r"(a[0]), "r"(a[1]), "r"(a[2]), "r"(a[3]), "r"(b[0]), "r"(b[1]));
}
__device__ __forceinline__ uint32_t pack_hi(float a, float b) {
    __half2 h = __floats2half2_rn(a, b);
    return *(uint32_t*)&h;
}
__device__ __forceinline__ void cpa16(uint32_t dst, const void* src) {
    asm volatile("cp.async.cg.shared.global [%0], [%1], 16;" :: "r"(dst), "l"(src));
}
#define CP_COMMIT() asm volatile("cp.async.commit_group;" ::: "memory")
#define CP_WAIT1()  asm volatile("cp.async.wait_group 1;" ::: "memory")
#define CP_WAIT0()  asm volatile("cp.async.wait_group 0;" ::: "memory")

// ---------------------------------------------------------------------------
// One-shot conversion kernel: x plain; Wq/Wk rope-pair-permuted; Wv, Wo plain.
// ---------------------------------------------------------------------------
#define XU  (MROWS*DIN/4)
#define WQU (DIN*NH*32)
#define WKU (DIN*NKV*32)
#define WVU (DIN*DKV/4)
#define WOU (DOUT*DOUT/4)
#define CONV_TOTAL (XU + WQU + WKU + WVU + WOU)

__global__ void conv_all(const float* __restrict__ x,
                         const float* __restrict__ Wq, const float* __restrict__ Wk,
                         const float* __restrict__ Wv, const float* __restrict__ Wo,
                         __half* __restrict__ xh, __half* __restrict__ wqkv,
                         __half* __restrict__ woh)
{
    int i = blockIdx.x * blockDim.x + threadIdx.x;
    if (i < XU) {
        float4 f = ((const float4*)x)[i];
        ((uint2*)xh)[i] = make_uint2(pack_hi(f.x, f.y), pack_hi(f.z, f.w));
        return;
    }
    i -= XU;
    if (i < WQU) {      // Wq permuted
        int k = i >> 9, h = (i >> 5) & 15, j2 = i & 31;
        const float* base = Wq + (size_t)k * DOUT + h * HD + j2 * 2;
        float2 a = *(const float2*)base;
        float2 b = *(const float2*)(base + 64);
        *(uint2*)(wqkv + (size_t)k * NQKV + h * HD + j2 * 4)
            = make_uint2(pack_hi(a.x, b.x), pack_hi(a.y, b.y));
        return;
    }
    i -= WQU;
    if (i < WKU) {      // Wk permuted
        int k = i >> 7, h = (i >> 5) & 3, j2 = i & 31;
        const float* base = Wk + (size_t)k * DKV + h * HD + j2 * 2;
        float2 a = *(const float2*)base;
        float2 b = *(const float2*)(base + 64);
        *(uint2*)(wqkv + (size_t)k * NQKV + DOUT + h * HD + j2 * 4)
            = make_uint2(pack_hi(a.x, b.x), pack_hi(a.y, b.y));
        return;
    }
    i -= WKU;
    if (i < WVU) {      // Wv plain
        int k = i >> 7, c4 = i & 127;
        float4 f = *(const float4*)(Wv + (size_t)k * DKV + c4 * 4);
        *(uint2*)(wqkv + (size_t)k * NQKV + DOUT + DKV + c4 * 4)
            = make_uint2(pack_hi(f.x, f.y), pack_hi(f.z, f.w));
        return;
    }
    i -= WVU;
    if (i < WOU) {      // Wo plain (dense)
        float4 f = ((const float4*)Wo)[i];
        ((uint2*)woh)[i] = make_uint2(pack_hi(f.x, f.y), pack_hi(f.z, f.w));
    }
}

// ---------------------------------------------------------------------------
// Shared GEMM mainloop (runtime K/N -> rolled chunk loop, small I-footprint)
// ---------------------------------------------------------------------------
#define KC    64
#define A_STR 72
#define B_STR 136
#define A_OFF 0
#define B_OFF 18432
#define STAGE 35840
#define GEMM_SMEM (2*STAGE)

#define GEMM_LOAD(k0, st)                                                            \
    {                                                                                \
        uint32_t base = sb + (st) * STAGE;                                           \
        _Pragma("unroll")                                                            \
        for (int i = 0; i < 4; i++) {                                                \
            int li = t + (i << 8);                                                   \
            int r = li >> 3, ch = li & 7;                                            \
            size_t so = (size_t)(row0 + r) * K + (k0) + ch * 8;                      \
            cpa16(base + A_OFF + (uint32_t)(r * A_STR + ch * 8) * 2, Ah + so);       \
        }                                                                            \
        _Pragma("unroll")                                                            \
        for (int i = 0; i < 4; i++) {                                                \
            int li = t + (i << 8);                                                   \
            int kk = li >> 4, ch = li & 15;                                          \
            size_t so = (size_t)((k0) + kk) * N + col0 + ch * 8;                     \
            cpa16(base + B_OFF + (uint32_t)(kk * B_STR + ch * 8) * 2, Bh + so);      \
        }                                                                            \
    }

#define GEMM_MAINLOOP()                                                              \
    GEMM_LOAD(0, 0);                                                                 \
    CP_COMMIT();                                                                     \
    GEMM_LOAD(KC, 1);                                                                \
    CP_COMMIT();                                                                     \
    for (int c = 0; c < nch; c++) {                                                  \
        CP_WAIT1();                                                                  \
        __syncthreads();                                                             \
        const uint32_t stb = sb + (c & 1) * STAGE;                                   \
        _Pragma("unroll")                                                            \
        for (int ks = 0; ks < 4; ks++) {                                             \
            uint32_t a[4][4];                                                        \
            _Pragma("unroll")                                                        \
            for (int mi = 0; mi < 4; mi++) {                                         \
                uint32_t ao = (uint32_t)((wm * 64 + mi * 16 + arow) * A_STR          \
                                         + ks * 16 + agrp) * 2;                      \
                ldsm_x4(a[mi][0], a[mi][1], a[mi][2], a[mi][3], stb + A_OFF + ao);   \
            }                                                                        \
            uint32_t b[4][2];                                                        \
            _Pragma("unroll")                                                        \
            for (int p = 0; p < 2; p++) {                                            \
                uint32_t bo = (uint32_t)((ks * 16 + arow) * B_STR                    \
                                         + wn * 32 + p * 16 + agrp) * 2;             \
                uint32_t r0, r1, r2, r3;                                             \
                ldsm_x4t(r0, r1, r2, r3, stb + B_OFF + bo);                          \
                b[2 * p][0] = r0;     b[2 * p][1] = r1;                              \
                b[2 * p + 1][0] = r2; b[2 * p + 1][1] = r3;                          \
            }                                                                        \
            _Pragma("unroll")                                                        \
            for (int mi = 0; mi < 4; mi++)                                           \
                _Pragma("unroll")                                                    \
                for (int nt = 0; nt < 4; nt++)                                       \
                    mma16816(acc[mi][nt], a[mi], b[nt]);                             \
        }                                                                            \
        __syncthreads();                                                             \
        if (c + 2 < nch) GEMM_LOAD((c + 2) * KC, (c & 1));                           \
        CP_COMMIT();                                                                 \
    }

// ---------------------------------------------------------------------------
// QKV GEMM with fused rope/scale/fp16 epilogue (runtime dims).
// q scale includes log2(e) so attention logits are natively base-2.
// ---------------------------------------------------------------------------
__global__ __launch_bounds__(256, 2) void gemm_qkv(
    const __half* __restrict__ Ah, const __half* __restrict__ Bh,
    const float* __restrict__ cosT, const float* __restrict__ sinT,
    __half* __restrict__ Qh, __half* __restrict__ Kh, __half* __restrict__ Vh,
    int M, int N, int K)
{
    extern __shared__ char smg[];
    const uint32_t sb = smem_u32(smg);
    const int t = threadIdx.x;
    const int wid = t >> 5, lane = t & 31;
    const int wm = wid >> 2, wn = wid & 3;
    const int row0 = blockIdx.y << 7, col0 = blockIdx.x << 7;
    const int nch = K / KC;

    float acc[4][4][4];
#pragma unroll
    for (int mi = 0; mi < 4; mi++)
#pragma unroll
        for (int nt = 0; nt < 4; nt++)
#pragma unroll
            for (int e = 0; e < 4; e++) acc[mi][nt][e] = 0.f;

    const int arow = lane & 15, agrp = (lane >> 4) << 3;

    GEMM_MAINLOOP();

    const int drow = lane >> 2, dcol = (lane & 3) * 2;
    const float scale = 0.08838834764831845f * 1.4426950408889634f; // /sqrt(HD) * log2(e)

    if (col0 < DOUT) {
        // q: rope + scale, permuted layout preserved
#pragma unroll
        for (int mi = 0; mi < 4; mi++) {
            int r = row0 + wm * 64 + mi * 16 + drow;
            int s0 = r & (Sq - 1), s1 = (r + 8) & (Sq - 1);
#pragma unroll
            for (int nt = 0; nt < 4; nt++) {
                int col = col0 + wn * 32 + nt * 8 + dcol;
                int jj = (col & 127) >> 1;
                float c0 = cosT[s0 * HD + jj], n0 = sinT[s0 * HD + jj];
                float c1 = cosT[s1 * HD + jj], n1 = sinT[s1 * HD + jj];
                float t1 = acc[mi][nt][0], t2 = acc[mi][nt][1];
                uint32_t p0 = pack_hi((t1 * c0 - t2 * n0) * scale,
                                      (t2 * c0 + t1 * n0) * scale);
                t1 = acc[mi][nt][2]; t2 = acc[mi][nt][3];
                uint32_t p1 = pack_hi((t1 * c1 - t2 * n1) * scale,
                                      (t2 * c1 + t1 * n1) * scale);
                *(uint32_t*)(Qh + (size_t)r * DOUT + col)       = p0;
                *(uint32_t*)(Qh + (size_t)(r + 8) * DOUT + col) = p1;
            }
        }
    } else if (col0 < DOUT + DKV) {
        // k: rope, permuted layout preserved
#pragma unroll
        for (int mi = 0; mi < 4; mi++) {
            int r = row0 + wm * 64 + mi * 16 + drow;
            int s0 = r & (Sq - 1), s1 = (r + 8) & (Sq - 1);
#pragma unroll
            for (int nt = 0; nt < 4; nt++) {
                int col = col0 + wn * 32 + nt * 8 + dcol;
                int kc = col - DOUT;
                int jj = (kc & 127) >> 1;
                float c0 = cosT[s0 * HD + jj], n0 = sinT[s0 * HD + jj];
                float c1 = cosT[s1 * HD + jj], n1 = sinT[s1 * HD + jj];
                float t1 = acc[mi][nt][0], t2 = acc[mi][nt][1];
                uint32_t p0 = pack_hi(t1 * c0 - t2 * n0, t2 * c0 + t1 * n0);
                t1 = acc[mi][nt][2]; t2 = acc[mi][nt][3];
                uint32_t p1 = pack_hi(t1 * c1 - t2 * n1, t2 * c1 + t1 * n1);
                *(uint32_t*)(Kh + (size_t)r * DKV + kc)       = p0;
                *(uint32_t*)(Kh + (size_t)(r + 8) * DKV + kc) = p1;
            }
        }
    } else {
        // v: plain fp16 convert
#pragma unroll
        for (int mi = 0; mi < 4; mi++) {
            int r = row0 + wm * 64 + mi * 16 + drow;
#pragma unroll
            for (int nt = 0; nt < 4; nt++) {
                int col = col0 + wn * 32 + nt * 8 + dcol;
                int vc = col - DOUT - DKV;
                *(uint32_t*)(Vh + (size_t)r * DKV + vc)
                    = pack_hi(acc[mi][nt][0], acc[mi][nt][1]);
                *(uint32_t*)(Vh + (size_t)(r + 8) * DKV + vc)
                    = pack_hi(acc[mi][nt][2], acc[mi][nt][3]);
            }
        }
    }
}

// ---------------------------------------------------------------------------
// Output-projection GEMM (plain fp32 epilogue, runtime dims).
// ---------------------------------------------------------------------------
__global__ __launch_bounds__(256, 2) void gemm_out(
    const __half* __restrict__ Ah, const __half* __restrict__ Bh,
    float* __restrict__ C, int M, int N, int K)
{
    extern __shared__ char smg[];
    const uint32_t sb = smem_u32(smg);
    const int t = threadIdx.x;
    const int wid = t >> 5, lane = t & 31;
    const int wm = wid >> 2, wn = wid & 3;
    const int row0 = blockIdx.y << 7, col0 = blockIdx.x << 7;
    const int nch = K / KC;

    float acc[4][4][4];
#pragma unroll
    for (int mi = 0; mi < 4; mi++)
#pragma unroll
        for (int nt = 0; nt < 4; nt++)
#pragma unroll
            for (int e = 0; e < 4; e++) acc[mi][nt][e] = 0.f;

    const int arow = lane & 15, agrp = (lane >> 4) << 3;

    GEMM_MAINLOOP();

    const int drow = lane >> 2, dcol = (lane & 3) * 2;
#pragma unroll
    for (int mi = 0; mi < 4; mi++) {
        int r = row0 + wm * 64 + mi * 16 + drow;
#pragma unroll
        for (int nt = 0; nt < 4; nt++) {
            int col = col0 + wn * 32 + nt * 8 + dcol;
            *(float2*)(C + (size_t)r * N + col)       = make_float2(acc[mi][nt][0], acc[mi][nt][1]);
            *(float2*)(C + (size_t)(r + 8) * N + col) = make_float2(acc[mi][nt][2], acc[mi][nt][3]);
        }
    }
}

// ---------------------------------------------------------------------------
// Tensor-core flash attention, single-pass fp16, base-2 softmax,
// 2 CTAs/SM co-residency (smem 104448*2 < 228KB; regs capped at 128).
// ---------------------------------------------------------------------------
#define FBM 128
#define FBN 64
#define F_STR 136
#define QH_OFF 0
#define KV0_OFF 34816
#define KV_STAGE 34816
#define FATTN_SMEM 104448

#define KV_LOAD(k0_, st)                                                             \
    {                                                                                \
        const __half* kb = Kh + ((size_t)b * Sq + (k0_)) * DKV + kh * HD;            \
        const __half* vb = Vh + ((size_t)b * Sq + (k0_)) * DKV + kh * HD;            \
        uint32_t kbase = sb + KV0_OFF + (st) * KV_STAGE;                             \
        _Pragma("unroll")                                                            \
        for (int i = 0; i < 4; i++) {                                                \
            int li = t + (i << 8);                                                   \
            int r = li >> 4, c8 = li & 15;                                           \
            uint32_t dof = (uint32_t)(r * F_STR + c8 * 8) * 2;                       \
            cpa16(kbase + dof,         kb + (size_t)r * DKV + c8 * 8);               \
            cpa16(kbase + 17408 + dof, vb + (size_t)r * DKV + c8 * 8);               \
        }                                                                            \
    }

__global__ __launch_bounds__(256, 2) void flash_attn_mma(
    const __half* __restrict__ Qh, const __half* __restrict__ Kh,
    const __half* __restrict__ Vh, __half* __restrict__ Oh)
{
    extern __shared__ char smf[];
    const uint32_t sb = smem_u32(smf);
    const int qtile = gridDim.x - 1 - blockIdx.x;
    const int h = blockIdx.y, b = blockIdx.z;
    const int kh = h >> 2;
    const int t = threadIdx.x;
    const int w = t >> 5, lane = t & 31;
    const int arow = lane & 15, agrp = (lane >> 4) << 3;
    const int q0 = qtile * FBM;

    {
        const __half* qb = Qh + ((size_t)b * Sq + q0) * DOUT + h * HD;
#pragma unroll
        for (int i = 0; i < 4; i++) {
            int li = t + (i << 8);
            int r = li >> 3, c8 = li & 7;
            uint32_t dof = (uint32_t)(r * F_STR + c8 * 16) * 2;
            cpa16(sb + QH_OFF + dof,      qb + (size_t)r * DOUT + c8 * 16);
            cpa16(sb + QH_OFF + dof + 16, qb + (size_t)r * DOUT + c8 * 16 + 8);
        }
    }
    KV_LOAD(0, 0);
    CP_COMMIT();

    float o[16][4];
#pragma unroll
    for (int nt = 0; nt < 16; nt++)
#pragma unroll
        for (int e = 0; e < 4; e++) o[nt][e] = 0.f;
    float m0 = -1e30f, m1 = -1e30f, l0 = 0.f, l1 = 0.f;

    const int wrow_max = q0 + w * 16 + 15;
    const int niter = (q0 + FBM) / FBN;

    for (int it = 0; it < niter; it++) {
        const int k0 = it * FBN;
        if (it + 1 < niter) {
            KV_LOAD((it + 1) * FBN, (it + 1) & 1);
            CP_COMMIT();
            CP_WAIT1();
        } else {
            CP_WAIT0();
        }
        __syncthreads();

        if (k0 <= wrow_max) {
            const uint32_t kvb = sb + KV0_OFF + (it & 1) * KV_STAGE;
            const uint32_t KHo = kvb, VHo = kvb + 17408;

            float s[8][4];
#pragma unroll
            for (int nt = 0; nt < 8; nt++)
#pragma unroll
                for (int e = 0; e < 4; e++) s[nt][e] = 0.f;

#pragma unroll
            for (int ks = 0; ks < 8; ks++) {
                uint32_t q[4];
                uint32_t qa = (uint32_t)((w * 16 + arow) * F_STR + ks * 16 + agrp) * 2;
                ldsm_x4(q[0], q[1], q[2], q[3], sb + QH_OFF + qa);
#pragma unroll
                for (int g = 0; g < 4; g++) {
                    uint32_t ka = (uint32_t)((g * 16 + arow) * F_STR + ks * 16 + agrp) * 2;
                    uint32_t h0, h1, h2, h3;
                    ldsm_x4(h0, h1, h2, h3, KHo + ka);
                    uint32_t b0[2] = {h0, h2}, b1[2] = {h1, h3};
                    mma16816(s[2 * g],     q, b0);
                    mma16816(s[2 * g + 1], q, b1);
                }
            }

            const int rg0 = q0 + w * 16 + (lane >> 2);
            if (k0 + FBN - 1 > q0 + w * 16) {
                int cg = k0 + 2 * (lane & 3);
#pragma unroll
                for (int nt = 0; nt < 8; nt++) {
                    int c = cg + nt * 8;
                    if (c     > rg0)     s[nt][0] = -1e30f;
                    if (c + 1 > rg0)     s[nt][1] = -1e30f;
                    if (c     > rg0 + 8) s[nt][2] = -1e30f;
                    if (c + 1 > rg0 + 8) s[nt][3] = -1e30f;
                }
            }

            float mx0 = -1e30f, mx1 = -1e30f;
#pragma unroll
            for (int nt = 0; nt < 8; nt++) {
                mx0 = fmaxf(mx0, fmaxf(s[nt][0], s[nt][1]));
                mx1 = fmaxf(mx1, fmaxf(s[nt][2], s[nt][3]));
            }
            mx0 = fmaxf(mx0, __shfl_xor_sync(0xffffffffu, mx0, 1));
            mx0 = fmaxf(mx0, __shfl_xor_sync(0xffffffffu, mx0, 2));
            mx1 = fmaxf(mx1, __shfl_xor_sync(0xffffffffu, mx1, 1));
            mx1 = fmaxf(mx1, __shfl_xor_sync(0xffffffffu, mx1, 2));
            float mn0 = fmaxf(m0, mx0), mn1 = fmaxf(m1, mx1);
            float a0 = exp2f(m0 - mn0), a1 = exp2f(m1 - mn1);
            m0 = mn0; m1 = mn1;

            float sum0 = 0.f, sum1 = 0.f;
#pragma unroll
            for (int nt = 0; nt < 8; nt++) {
                s[nt][0] = exp2f(s[nt][0] - mn0);
                s[nt][1] = exp2f(s[nt][1] - mn0);
                s[nt][2] = exp2f(s[nt][2] - mn1);
                s[nt][3] = exp2f(s[nt][3] - mn1);
                sum0 += s[nt][0] + s[nt][1];
                sum1 += s[nt][2] + s[nt][3];
            }
            sum0 += __shfl_xor_sync(0xffffffffu, sum0, 1);
            sum0 += __shfl_xor_sync(0xffffffffu, sum0, 2);
            sum1 += __shfl_xor_sync(0xffffffffu, sum1, 1);
            sum1 += __shfl_xor_sync(0xffffffffu, sum1, 2);
            l0 = l0 * a0 + sum0;
            l1 = l1 * a1 + sum1;

#pragma unroll
            for (int nt = 0; nt < 16; nt++) {
                o[nt][0] *= a0; o[nt][1] *= a0;
                o[nt][2] *= a1; o[nt][3] *= a1;
            }

            uint32_t ap[4][4];
#pragma unroll
            for (int ts = 0; ts < 4; ts++) {
                ap[ts][0] = pack_hi(s[2 * ts][0],     s[2 * ts][1]);
                ap[ts][1] = pack_hi(s[2 * ts][2],     s[2 * ts][3]);
                ap[ts][2] = pack_hi(s[2 * ts + 1][0], s[2 * ts + 1][1]);
                ap[ts][3] = pack_hi(s[2 * ts + 1][2], s[2 * ts + 1][3]);
            }

#pragma unroll
            for (int ts = 0; ts < 4; ts++) {
#pragma unroll
                for (int g = 0; g < 8; g++) {
                    uint32_t va = (uint32_t)((ts * 16 + arow) * F_STR + g * 16 + agrp) * 2;
                    uint32_t h0, h1, h2, h3;
                    ldsm_x4t(h0, h1, h2, h3, VHo + va);
                    uint32_t b0[2] = {h0, h1}, b1[2] = {h2, h3};
                    mma16816(o[2 * g],     ap[ts], b0);
                    mma16816(o[2 * g + 1], ap[ts], b1);
                }
            }
        }
        __syncthreads();
    }

    float inv0 = 1.f / l0, inv1 = 1.f / l1;
    const int rg0 = q0 + w * 16 + (lane >> 2);
    size_t base0 = ((size_t)b * Sq + rg0) * DOUT + h * HD + 2 * (lane & 3);
    size_t base1 = base0 + (size_t)8 * DOUT;
#pragma unroll
    for (int nt = 0; nt < 16; nt++) {
        ((uint32_t*)Oh)[(base0 + nt * 8) >> 1] = pack_hi(o[nt][0] * inv0, o[nt][1] * inv0);
        ((uint32_t*)Oh)[(base1 + nt * 8) >> 1] = pack_hi(o[nt][2] * inv1, o[nt][3] * inv1);
    }
}

// ---------------------------------------------------------------------------
extern "C" void kernel_launch(void* const* d_in, const int* in_sizes, int n_in,
                              void* d_out, int out_size)
{
    const float* x    = (const float*)d_in[0];
    const float* Wq   = (const float*)d_in[1];
    const float* Wk   = (const float*)d_in[2];
    const float* Wv   = (const float*)d_in[3];
    const float* Wo   = (const float*)d_in[4];
    const float* cosT = (const float*)d_in[5];
    const float* sinT = (const float*)d_in[6];
    float* out = (float*)d_out;

    __half *xh, *wqkv, *woh, *qh, *khb, *vhb, *ch;
    cudaGetSymbolAddress((void**)&xh,   g_xh);
    cudaGetSymbolAddress((void**)&wqkv, g_wqkv);
    cudaGetSymbolAddress((void**)&woh,  g_woh);
    cudaGetSymbolAddress((void**)&qh,   g_qh);
    cudaGetSymbolAddress((void**)&khb,  g_kh);
    cudaGetSymbolAddress((void**)&vhb,  g_vh);
    cudaGetSymbolAddress((void**)&ch,   g_ch);

    cudaFuncSetAttribute(gemm_qkv,       cudaFuncAttributeMaxDynamicSharedMemorySize, GEMM_SMEM);
    cudaFuncSetAttribute(gemm_out,       cudaFuncAttributeMaxDynamicSharedMemorySize, GEMM_SMEM);
    cudaFuncSetAttribute(flash_attn_mma, cudaFuncAttributeMaxDynamicSharedMemorySize, FATTN_SMEM);

    dim3 thr(256);
    // One-shot conversion (x + permuted Wq/Wk + Wv + Wo)
    conv_all<<<(CONV_TOTAL + 255) / 256, thr>>>(x, Wq, Wk, Wv, Wo, xh, wqkv, woh);

    // Fused QKV projection + rope + scale(log2e) + fp16
    gemm_qkv<<<dim3(NQKV / 128, MROWS / 128), thr, GEMM_SMEM>>>(
        xh, wqkv, cosT, sinT, qh, khb, vhb, MROWS, NQKV, DIN);

    // Attention (base-2 softmax, 2 CTAs/SM) -> fp16 ctx
    flash_attn_mma<<<dim3(Sq / FBM, NH, Bb), thr, FATTN_SMEM>>>(qh, khb, vhb, ch);

    // Output projection
    gemm_out<<<dim3(DOUT / 128, MROWS / 128), thr, GEMM_SMEM>>>(ch, woh, out, MROWS, DOUT, DOUT);
}

// round 16
// speedup vs baseline: 1.0245x; 1.0245x over previous
#include <cuda_runtime.h>
#include <cuda_fp16.h>
#include <cstdint>

// Problem constants
#define Bb    2
#define Sq    2048
#define DIN   2048
#define DOUT  2048
#define NH    16
#define NKV   4
#define HD    128
#define MROWS (Bb*Sq)        // 4096
#define DKV   (NKV*HD)       // 512
#define NQKV  (DOUT + 2*DKV) // 3072

// Scratch
__device__ __half g_xh[(size_t)MROWS*DIN];
__device__ __half g_wqkv[(size_t)DIN*NQKV];   // Wq,Wk rope-pair permuted; Wv plain
__device__ __half g_woh[(size_t)DOUT*DOUT];
__device__ __half g_qh[(size_t)MROWS*DOUT];   // permuted d, rope applied, scaled by log2e/sqrt(HD)
__device__ __half g_kh[(size_t)MROWS*DKV];    // permuted d, rope applied
__device__ __half g_vh[(size_t)MROWS*DKV];
__device__ __half g_ch[(size_t)MROWS*DOUT];

// ---------------------------------------------------------------------------
// Helpers
// ---------------------------------------------------------------------------
__device__ __forceinline__ uint32_t smem_u32(const void* p) {
    uint32_t a;
    asm("{ .reg .u64 t; cvta.to.shared.u64 t, %1; cvt.u32.u64 %0, t; }" : "=r"(a) : "l"(p));
    return a;
}
__device__ __forceinline__ void ldsm_x4(uint32_t& r0, uint32_t& r1, uint32_t& r2, uint32_t& r3,
                                        uint32_t addr) {
    asm volatile("ldmatrix.sync.aligned.m8n8.x4.shared.b16 {%0,%1,%2,%3}, [%4];"
                 : "=r"(r0), "=r"(r1), "=r"(r2), "=r"(r3) : "r"(addr));
}
__device__ __forceinline__ void ldsm_x4t(uint32_t& r0, uint32_t& r1, uint32_t& r2, uint32_t& r3,
                                         uint32_t addr) {
    asm volatile("ldmatrix.sync.aligned.m8n8.x4.trans.shared.b16 {%0,%1,%2,%3}, [%4];"
                 : "=r"(r0), "=r"(r1), "=r"(r2), "=r"(r3) : "r"(addr));
}
__device__ __forceinline__ void mma16816(float* d, const uint32_t* a, const uint32_t* b) {
    asm volatile(
        "mma.sync.aligned.m16n8k16.row.col.f32.f16.f16.f32 "
        "{%0,%1,%2,%3}, {%4,%5,%6,%7}, {%8,%9}, {%0,%1,%2,%3};"
        : "+f"(d[0]), "+f"(d[1]), "+f"(d[2]), "+f"(d[3])
        : "r"(a[0]), "r"(a[1]), "r"(a[2]), "r"(a[3]), "r"(b[0]), "r"(b[1]));
}
__device__ __forceinline__ uint32_t pack_hi(float a, float b) {
    __half2 h = __floats2half2_rn(a, b);
    return *(uint32_t*)&h;
}
__device__ __forceinline__ void cpa16(uint32_t dst, const void* src) {
    asm volatile("cp.async.cg.shared.global [%0], [%1], 16;" :: "r"(dst), "l"(src));
}
#define CP_COMMIT() asm volatile("cp.async.commit_group;" ::: "memory")
#define CP_WAIT1()  asm volatile("cp.async.wait_group 1;" ::: "memory")
#define CP_WAIT0()  asm volatile("cp.async.wait_group 0;" ::: "memory")

// ---------------------------------------------------------------------------
// One-shot conversion kernel: x plain; Wq/Wk rope-pair-permuted; Wv, Wo plain.
// ---------------------------------------------------------------------------
#define XU  (MROWS*DIN/4)
#define WQU (DIN*NH*32)
#define WKU (DIN*NKV*32)
#define WVU (DIN*DKV/4)
#define WOU (DOUT*DOUT/4)
#define CONV_TOTAL (XU + WQU + WKU + WVU + WOU)

__global__ void conv_all(const float* __restrict__ x,
                         const float* __restrict__ Wq, const float* __restrict__ Wk,
                         const float* __restrict__ Wv, const float* __restrict__ Wo,
                         __half* __restrict__ xh, __half* __restrict__ wqkv,
                         __half* __restrict__ woh)
{
    int i = blockIdx.x * blockDim.x + threadIdx.x;
    if (i < XU) {
        float4 f = ((const float4*)x)[i];
        ((uint2*)xh)[i] = make_uint2(pack_hi(f.x, f.y), pack_hi(f.z, f.w));
        return;
    }
    i -= XU;
    if (i < WQU) {      // Wq permuted
        int k = i >> 9, h = (i >> 5) & 15, j2 = i & 31;
        const float* base = Wq + (size_t)k * DOUT + h * HD + j2 * 2;
        float2 a = *(const float2*)base;
        float2 b = *(const float2*)(base + 64);
        *(uint2*)(wqkv + (size_t)k * NQKV + h * HD + j2 * 4)
            = make_uint2(pack_hi(a.x, b.x), pack_hi(a.y, b.y));
        return;
    }
    i -= WQU;
    if (i < WKU) {      // Wk permuted
        int k = i >> 7, h = (i >> 5) & 3, j2 = i & 31;
        const float* base = Wk + (size_t)k * DKV + h * HD + j2 * 2;
        float2 a = *(const float2*)base;
        float2 b = *(const float2*)(base + 64);
        *(uint2*)(wqkv + (size_t)k * NQKV + DOUT + h * HD + j2 * 4)
            = make_uint2(pack_hi(a.x, b.x), pack_hi(a.y, b.y));
        return;
    }
    i -= WKU;
    if (i < WVU) {      // Wv plain
        int k = i >> 7, c4 = i & 127;
        float4 f = *(const float4*)(Wv + (size_t)k * DKV + c4 * 4);
        *(uint2*)(wqkv + (size_t)k * NQKV + DOUT + DKV + c4 * 4)
            = make_uint2(pack_hi(f.x, f.y), pack_hi(f.z, f.w));
        return;
    }
    i -= WVU;
    if (i < WOU) {      // Wo plain (dense)
        float4 f = ((const float4*)Wo)[i];
        ((uint2*)woh)[i] = make_uint2(pack_hi(f.x, f.y), pack_hi(f.z, f.w));
    }
}

// ---------------------------------------------------------------------------
// Shared GEMM mainloop: runtime K/N, chunk loop unrolled x2
// (double body ~2.5KB SASS -> always L0-resident, no I$ bistability).
// ---------------------------------------------------------------------------
#define KC    64
#define A_STR 72
#define B_STR 136
#define A_OFF 0
#define B_OFF 18432
#define STAGE 35840
#define GEMM_SMEM (2*STAGE)

#define GEMM_LOAD(k0, st)                                                            \
    {                                                                                \
        uint32_t base = sb + (st) * STAGE;                                           \
        _Pragma("unroll")                                                            \
        for (int i = 0; i < 4; i++) {                                                \
            int li = t + (i << 8);                                                   \
            int r = li >> 3, ch = li & 7;                                            \
            size_t so = (size_t)(row0 + r) * K + (k0) + ch * 8;                      \
            cpa16(base + A_OFF + (uint32_t)(r * A_STR + ch * 8) * 2, Ah + so);       \
        }                                                                            \
        _Pragma("unroll")                                                            \
        for (int i = 0; i < 4; i++) {                                                \
            int li = t + (i << 8);                                                   \
            int kk = li >> 4, ch = li & 15;                                          \
            size_t so = (size_t)((k0) + kk) * N + col0 + ch * 8;                     \
            cpa16(base + B_OFF + (uint32_t)(kk * B_STR + ch * 8) * 2, Bh + so);      \
        }                                                                            \
    }

#define GEMM_MAINLOOP()                                                              \
    GEMM_LOAD(0, 0);                                                                 \
    CP_COMMIT();                                                                     \
    GEMM_LOAD(KC, 1);                                                                \
    CP_COMMIT();                                                                     \
    _Pragma("unroll 2")                                                              \
    for (int c = 0; c < nch; c++) {                                                  \
        CP_WAIT1();                                                                  \
        __syncthreads();                                                             \
        const uint32_t stb = sb + (c & 1) * STAGE;                                   \
        _Pragma("unroll")                                                            \
        for (int ks = 0; ks < 4; ks++) {                                             \
            uint32_t a[4][4];                                                        \
            _Pragma("unroll")                                                        \
            for (int mi = 0; mi < 4; mi++) {                                         \
                uint32_t ao = (uint32_t)((wm * 64 + mi * 16 + arow) * A_STR          \
                                         + ks * 16 + agrp) * 2;                      \
                ldsm_x4(a[mi][0], a[mi][1], a[mi][2], a[mi][3], stb + A_OFF + ao);   \
            }                                                                        \
            uint32_t b[4][2];                                                        \
            _Pragma("unroll")                                                        \
            for (int p = 0; p < 2; p++) {                                            \
                uint32_t bo = (uint32_t)((ks * 16 + arow) * B_STR                    \
                                         + wn * 32 + p * 16 + agrp) * 2;             \
                uint32_t r0, r1, r2, r3;                                             \
                ldsm_x4t(r0, r1, r2, r3, stb + B_OFF + bo);                          \
                b[2 * p][0] = r0;     b[2 * p][1] = r1;                              \
                b[2 * p + 1][0] = r2; b[2 * p + 1][1] = r3;                          \
            }                                                                        \
            _Pragma("unroll")                                                        \
            for (int mi = 0; mi < 4; mi++)                                           \
                _Pragma("unroll")                                                    \
                for (int nt = 0; nt < 4; nt++)                                       \
                    mma16816(acc[mi][nt], a[mi], b[nt]);                             \
        }                                                                            \
        __syncthreads();                                                             \
        if (c + 2 < nch) GEMM_LOAD((c + 2) * KC, (c & 1));                           \
        CP_COMMIT();                                                                 \
    }

// ---------------------------------------------------------------------------
// QKV GEMM with fused rope/scale/fp16 epilogue (runtime dims).
// q scale includes log2(e) so attention logits are natively base-2.
// ---------------------------------------------------------------------------
__global__ __launch_bounds__(256, 2) void gemm_qkv(
    const __half* __restrict__ Ah, const __half* __restrict__ Bh,
    const float* __restrict__ cosT, const float* __restrict__ sinT,
    __half* __restrict__ Qh, __half* __restrict__ Kh, __half* __restrict__ Vh,
    int M, int N, int K)
{
    extern __shared__ char smg[];
    const uint32_t sb = smem_u32(smg);
    const int t = threadIdx.x;
    const int wid = t >> 5, lane = t & 31;
    const int wm = wid >> 2, wn = wid & 3;
    const int row0 = blockIdx.y << 7, col0 = blockIdx.x << 7;
    const int nch = K / KC;

    float acc[4][4][4];
#pragma unroll
    for (int mi = 0; mi < 4; mi++)
#pragma unroll
        for (int nt = 0; nt < 4; nt++)
#pragma unroll
            for (int e = 0; e < 4; e++) acc[mi][nt][e] = 0.f;

    const int arow = lane & 15, agrp = (lane >> 4) << 3;

    GEMM_MAINLOOP();

    const int drow = lane >> 2, dcol = (lane & 3) * 2;
    const float scale = 0.08838834764831845f * 1.4426950408889634f; // /sqrt(HD) * log2(e)

    if (col0 < DOUT) {
        // q: rope + scale, permuted layout preserved
#pragma unroll
        for (int mi = 0; mi < 4; mi++) {
            int r = row0 + wm * 64 + mi * 16 + drow;
            int s0 = r & (Sq - 1), s1 = (r + 8) & (Sq - 1);
#pragma unroll
            for (int nt = 0; nt < 4; nt++) {
                int col = col0 + wn * 32 + nt * 8 + dcol;
                int jj = (col & 127) >> 1;
                float c0 = cosT[s0 * HD + jj], n0 = sinT[s0 * HD + jj];
                float c1 = cosT[s1 * HD + jj], n1 = sinT[s1 * HD + jj];
                float t1 = acc[mi][nt][0], t2 = acc[mi][nt][1];
                uint32_t p0 = pack_hi((t1 * c0 - t2 * n0) * scale,
                                      (t2 * c0 + t1 * n0) * scale);
                t1 = acc[mi][nt][2]; t2 = acc[mi][nt][3];
                uint32_t p1 = pack_hi((t1 * c1 - t2 * n1) * scale,
                                      (t2 * c1 + t1 * n1) * scale);
                *(uint32_t*)(Qh + (size_t)r * DOUT + col)       = p0;
                *(uint32_t*)(Qh + (size_t)(r + 8) * DOUT + col) = p1;
            }
        }
    } else if (col0 < DOUT + DKV) {
        // k: rope, permuted layout preserved
#pragma unroll
        for (int mi = 0; mi < 4; mi++) {
            int r = row0 + wm * 64 + mi * 16 + drow;
            int s0 = r & (Sq - 1), s1 = (r + 8) & (Sq - 1);
#pragma unroll
            for (int nt = 0; nt < 4; nt++) {
                int col = col0 + wn * 32 + nt * 8 + dcol;
                int kc = col - DOUT;
                int jj = (kc & 127) >> 1;
                float c0 = cosT[s0 * HD + jj], n0 = sinT[s0 * HD + jj];
                float c1 = cosT[s1 * HD + jj], n1 = sinT[s1 * HD + jj];
                float t1 = acc[mi][nt][0], t2 = acc[mi][nt][1];
                uint32_t p0 = pack_hi(t1 * c0 - t2 * n0, t2 * c0 + t1 * n0);
                t1 = acc[mi][nt][2]; t2 = acc[mi][nt][3];
                uint32_t p1 = pack_hi(t1 * c1 - t2 * n1, t2 * c1 + t1 * n1);
                *(uint32_t*)(Kh + (size_t)r * DKV + kc)       = p0;
                *(uint32_t*)(Kh + (size_t)(r + 8) * DKV + kc) = p1;
            }
        }
    } else {
        // v: plain fp16 convert
#pragma unroll
        for (int mi = 0; mi < 4; mi++) {
            int r = row0 + wm * 64 + mi * 16 + drow;
#pragma unroll
            for (int nt = 0; nt < 4; nt++) {
                int col = col0 + wn * 32 + nt * 8 + dcol;
                int vc = col - DOUT - DKV;
                *(uint32_t*)(Vh + (size_t)r * DKV + vc)
                    = pack_hi(acc[mi][nt][0], acc[mi][nt][1]);
                *(uint32_t*)(Vh + (size_t)(r + 8) * DKV + vc)
                    = pack_hi(acc[mi][nt][2], acc[mi][nt][3]);
            }
        }
    }
}

// ---------------------------------------------------------------------------
// Output-projection GEMM (plain fp32 epilogue, runtime dims).
// ---------------------------------------------------------------------------
__global__ __launch_bounds__(256, 2) void gemm_out(
    const __half* __restrict__ Ah, const __half* __restrict__ Bh,
    float* __restrict__ C, int M, int N, int K)
{
    extern __shared__ char smg[];
    const uint32_t sb = smem_u32(smg);
    const int t = threadIdx.x;
    const int wid = t >> 5, lane = t & 31;
    const int wm = wid >> 2, wn = wid & 3;
    const int row0 = blockIdx.y << 7, col0 = blockIdx.x << 7;
    const int nch = K / KC;

    float acc[4][4][4];
#pragma unroll
    for (int mi = 0; mi < 4; mi++)
#pragma unroll
        for (int nt = 0; nt < 4; nt++)
#pragma unroll
            for (int e = 0; e < 4; e++) acc[mi][nt][e] = 0.f;

    const int arow = lane & 15, agrp = (lane >> 4) << 3;

    GEMM_MAINLOOP();

    const int drow = lane >> 2, dcol = (lane & 3) * 2;
#pragma unroll
    for (int mi = 0; mi < 4; mi++) {
        int r = row0 + wm * 64 + mi * 16 + drow;
#pragma unroll
        for (int nt = 0; nt < 4; nt++) {
            int col = col0 + wn * 32 + nt * 8 + dcol;
            *(float2*)(C + (size_t)r * N + col)       = make_float2(acc[mi][nt][0], acc[mi][nt][1]);
            *(float2*)(C + (size_t)(r + 8) * N + col) = make_float2(acc[mi][nt][2], acc[mi][nt][3]);
        }
    }
}

// ---------------------------------------------------------------------------
// Tensor-core flash attention, single-pass fp16, base-2 softmax,
// 1 CTA/SM (no register cap -> no spill; R15's (256,2) regressed).
// ---------------------------------------------------------------------------
#define FBM 128
#define FBN 64
#define F_STR 136
#define QH_OFF 0
#define KV0_OFF 34816
#define KV_STAGE 34816
#define FATTN_SMEM 104448

#define KV_LOAD(k0_, st)                                                             \
    {                                                                                \
        const __half* kb = Kh + ((size_t)b * Sq + (k0_)) * DKV + kh * HD;            \
        const __half* vb = Vh + ((size_t)b * Sq + (k0_)) * DKV + kh * HD;            \
        uint32_t kbase = sb + KV0_OFF + (st) * KV_STAGE;                             \
        _Pragma("unroll")                                                            \
        for (int i = 0; i < 4; i++) {                                                \
            int li = t + (i << 8);                                                   \
            int r = li >> 4, c8 = li & 15;                                           \
            uint32_t dof = (uint32_t)(r * F_STR + c8 * 8) * 2;                       \
            cpa16(kbase + dof,         kb + (size_t)r * DKV + c8 * 8);               \
            cpa16(kbase + 17408 + dof, vb + (size_t)r * DKV + c8 * 8);               \
        }                                                                            \
    }

__global__ __launch_bounds__(256, 1) void flash_attn_mma(
    const __half* __restrict__ Qh, const __half* __restrict__ Kh,
    const __half* __restrict__ Vh, __half* __restrict__ Oh)
{
    extern __shared__ char smf[];
    const uint32_t sb = smem_u32(smf);
    const int qtile = gridDim.x - 1 - blockIdx.x;
    const int h = blockIdx.y, b = blockIdx.z;
    const int kh = h >> 2;
    const int t = threadIdx.x;
    const int w = t >> 5, lane = t & 31;
    const int arow = lane & 15, agrp = (lane >> 4) << 3;
    const int q0 = qtile * FBM;

    {
        const __half* qb = Qh + ((size_t)b * Sq + q0) * DOUT + h * HD;
#pragma unroll
        for (int i = 0; i < 4; i++) {
            int li = t + (i << 8);
            int r = li >> 3, c8 = li & 7;
            uint32_t dof = (uint32_t)(r * F_STR + c8 * 16) * 2;
            cpa16(sb + QH_OFF + dof,      qb + (size_t)r * DOUT + c8 * 16);
            cpa16(sb + QH_OFF + dof + 16, qb + (size_t)r * DOUT + c8 * 16 + 8);
        }
    }
    KV_LOAD(0, 0);
    CP_COMMIT();

    float o[16][4];
#pragma unroll
    for (int nt = 0; nt < 16; nt++)
#pragma unroll
        for (int e = 0; e < 4; e++) o[nt][e] = 0.f;
    float m0 = -1e30f, m1 = -1e30f, l0 = 0.f, l1 = 0.f;

    const int wrow_max = q0 + w * 16 + 15;
    const int niter = (q0 + FBM) / FBN;

    for (int it = 0; it < niter; it++) {
        const int k0 = it * FBN;
        if (it + 1 < niter) {
            KV_LOAD((it + 1) * FBN, (it + 1) & 1);
            CP_COMMIT();
            CP_WAIT1();
        } else {
            CP_WAIT0();
        }
        __syncthreads();

        if (k0 <= wrow_max) {
            const uint32_t kvb = sb + KV0_OFF + (it & 1) * KV_STAGE;
            const uint32_t KHo = kvb, VHo = kvb + 17408;

            float s[8][4];
#pragma unroll
            for (int nt = 0; nt < 8; nt++)
#pragma unroll
                for (int e = 0; e < 4; e++) s[nt][e] = 0.f;

#pragma unroll
            for (int ks = 0; ks < 8; ks++) {
                uint32_t q[4];
                uint32_t qa = (uint32_t)((w * 16 + arow) * F_STR + ks * 16 + agrp) * 2;
                ldsm_x4(q[0], q[1], q[2], q[3], sb + QH_OFF + qa);
#pragma unroll
                for (int g = 0; g < 4; g++) {
                    uint32_t ka = (uint32_t)((g * 16 + arow) * F_STR + ks * 16 + agrp) * 2;
                    uint32_t h0, h1, h2, h3;
                    ldsm_x4(h0, h1, h2, h3, KHo + ka);
                    uint32_t b0[2] = {h0, h2}, b1[2] = {h1, h3};
                    mma16816(s[2 * g],     q, b0);
                    mma16816(s[2 * g + 1], q, b1);
                }
            }

            const int rg0 = q0 + w * 16 + (lane >> 2);
            if (k0 + FBN - 1 > q0 + w * 16) {
                int cg = k0 + 2 * (lane & 3);
#pragma unroll
                for (int nt = 0; nt < 8; nt++) {
                    int c = cg + nt * 8;
                    if (c     > rg0)     s[nt][0] = -1e30f;
                    if (c + 1 > rg0)     s[nt][1] = -1e30f;
                    if (c     > rg0 + 8) s[nt][2] = -1e30f;
                    if (c + 1 > rg0 + 8) s[nt][3] = -1e30f;
                }
            }

            float mx0 = -1e30f, mx1 = -1e30f;
#pragma unroll
            for (int nt = 0; nt < 8; nt++) {
                mx0 = fmaxf(mx0, fmaxf(s[nt][0], s[nt][1]));
                mx1 = fmaxf(mx1, fmaxf(s[nt][2], s[nt][3]));
            }
            mx0 = fmaxf(mx0, __shfl_xor_sync(0xffffffffu, mx0, 1));
            mx0 = fmaxf(mx0, __shfl_xor_sync(0xffffffffu, mx0, 2));
            mx1 = fmaxf(mx1, __shfl_xor_sync(0xffffffffu, mx1, 1));
            mx1 = fmaxf(mx1, __shfl_xor_sync(0xffffffffu, mx1, 2));
            float mn0 = fmaxf(m0, mx0), mn1 = fmaxf(m1, mx1);
            float a0 = exp2f(m0 - mn0), a1 = exp2f(m1 - mn1);
            m0 = mn0; m1 = mn1;

            float sum0 = 0.f, sum1 = 0.f;
#pragma unroll
            for (int nt = 0; nt < 8; nt++) {
                s[nt][0] = exp2f(s[nt][0] - mn0);
                s[nt][1] = exp2f(s[nt][1] - mn0);
                s[nt][2] = exp2f(s[nt][2] - mn1);
                s[nt][3] = exp2f(s[nt][3] - mn1);
                sum0 += s[nt][0] + s[nt][1];
                sum1 += s[nt][2] + s[nt][3];
            }
            sum0 += __shfl_xor_sync(0xffffffffu, sum0, 1);
            sum0 += __shfl_xor_sync(0xffffffffu, sum0, 2);
            sum1 += __shfl_xor_sync(0xffffffffu, sum1, 1);
            sum1 += __shfl_xor_sync(0xffffffffu, sum1, 2);
            l0 = l0 * a0 + sum0;
            l1 = l1 * a1 + sum1;

#pragma unroll
            for (int nt = 0; nt < 16; nt++) {
                o[nt][0] *= a0; o[nt][1] *= a0;
                o[nt][2] *= a1; o[nt][3] *= a1;
            }

            uint32_t ap[4][4];
#pragma unroll
            for (int ts = 0; ts < 4; ts++) {
                ap[ts][0] = pack_hi(s[2 * ts][0],     s[2 * ts][1]);
                ap[ts][1] = pack_hi(s[2 * ts][2],     s[2 * ts][3]);
                ap[ts][2] = pack_hi(s[2 * ts + 1][0], s[2 * ts + 1][1]);
                ap[ts][3] = pack_hi(s[2 * ts + 1][2], s[2 * ts + 1][3]);
            }

#pragma unroll
            for (int ts = 0; ts < 4; ts++) {
#pragma unroll
                for (int g = 0; g < 8; g++) {
                    uint32_t va = (uint32_t)((ts * 16 + arow) * F_STR + g * 16 + agrp) * 2;
                    uint32_t h0, h1, h2, h3;
                    ldsm_x4t(h0, h1, h2, h3, VHo + va);
                    uint32_t b0[2] = {h0, h1}, b1[2] = {h2, h3};
                    mma16816(o[2 * g],     ap[ts], b0);
                    mma16816(o[2 * g + 1], ap[ts], b1);
                }
            }
        }
        __syncthreads();
    }

    float inv0 = 1.f / l0, inv1 = 1.f / l1;
    const int rg0 = q0 + w * 16 + (lane >> 2);
    size_t base0 = ((size_t)b * Sq + rg0) * DOUT + h * HD + 2 * (lane & 3);
    size_t base1 = base0 + (size_t)8 * DOUT;
#pragma unroll
    for (int nt = 0; nt < 16; nt++) {
        ((uint32_t*)Oh)[(base0 + nt * 8) >> 1] = pack_hi(o[nt][0] * inv0, o[nt][1] * inv0);
        ((uint32_t*)Oh)[(base1 + nt * 8) >> 1] = pack_hi(o[nt][2] * inv1, o[nt][3] * inv1);
    }
}

// ---------------------------------------------------------------------------
extern "C" void kernel_launch(void* const* d_in, const int* in_sizes, int n_in,
                              void* d_out, int out_size)
{
    const float* x    = (const float*)d_in[0];
    const float* Wq   = (const float*)d_in[1];
    const float* Wk   = (const float*)d_in[2];
    const float* Wv   = (const float*)d_in[3];
    const float* Wo   = (const float*)d_in[4];
    const float* cosT = (const float*)d_in[5];
    const float* sinT = (const float*)d_in[6];
    float* out = (float*)d_out;

    __half *xh, *wqkv, *woh, *qh, *khb, *vhb, *ch;
    cudaGetSymbolAddress((void**)&xh,   g_xh);
    cudaGetSymbolAddress((void**)&wqkv, g_wqkv);
    cudaGetSymbolAddress((void**)&woh,  g_woh);
    cudaGetSymbolAddress((void**)&qh,   g_qh);
    cudaGetSymbolAddress((void**)&khb,  g_kh);
    cudaGetSymbolAddress((void**)&vhb,  g_vh);
    cudaGetSymbolAddress((void**)&ch,   g_ch);

    cudaFuncSetAttribute(gemm_qkv,       cudaFuncAttributeMaxDynamicSharedMemorySize, GEMM_SMEM);
    cudaFuncSetAttribute(gemm_out,       cudaFuncAttributeMaxDynamicSharedMemorySize, GEMM_SMEM);
    cudaFuncSetAttribute(flash_attn_mma, cudaFuncAttributeMaxDynamicSharedMemorySize, FATTN_SMEM);

    dim3 thr(256);
    // One-shot conversion (x + permuted Wq/Wk + Wv + Wo)
    conv_all<<<(CONV_TOTAL + 255) / 256, thr>>>(x, Wq, Wk, Wv, Wo, xh, wqkv, woh);

    // Fused QKV projection + rope + scale(log2e) + fp16
    gemm_qkv<<<dim3(NQKV / 128, MROWS / 128), thr, GEMM_SMEM>>>(
        xh, wqkv, cosT, sinT, qh, khb, vhb, MROWS, NQKV, DIN);

    // Attention (base-2 softmax, 1 CTA/SM) -> fp16 ctx
    flash_attn_mma<<<dim3(Sq / FBM, NH, Bb), thr, FATTN_SMEM>>>(qh, khb, vhb, ch);

    // Output projection
    gemm_out<<<dim3(DOUT / 128, MROWS / 128), thr, GEMM_SMEM>>>(ch, woh, out, MROWS, DOUT, DOUT);
}

// round 17
// speedup vs baseline: 1.0356x; 1.0108x over previous
#include <cuda_runtime.h>
#include <cuda_fp16.h>
#include <cstdint>

// Problem constants
#define Bb    2
#define Sq    2048
#define DIN   2048
#define DOUT  2048
#define NH    16
#define NKV   4
#define HD    128
#define MROWS (Bb*Sq)        // 4096
#define DKV   (NKV*HD)       // 512
#define NQKV  (DOUT + 2*DKV) // 3072

// Scratch
__device__ __half g_xh[(size_t)MROWS*DIN];
__device__ __half g_wqkv[(size_t)DIN*NQKV];   // Wq,Wk rope-pair permuted; Wv plain
__device__ __half g_woh[(size_t)DOUT*DOUT];
__device__ __half g_qh[(size_t)MROWS*DOUT];   // permuted d, rope applied, scaled by log2e/sqrt(HD)
__device__ __half g_kh[(size_t)MROWS*DKV];    // permuted d, rope applied
__device__ __half g_vh[(size_t)MROWS*DKV];
__device__ __half g_ch[(size_t)MROWS*DOUT];

// ---------------------------------------------------------------------------
// Helpers
// ---------------------------------------------------------------------------
__device__ __forceinline__ uint32_t smem_u32(const void* p) {
    uint32_t a;
    asm("{ .reg .u64 t; cvta.to.shared.u64 t, %1; cvt.u32.u64 %0, t; }" : "=r"(a) : "l"(p));
    return a;
}
__device__ __forceinline__ void ldsm_x4(uint32_t& r0, uint32_t& r1, uint32_t& r2, uint32_t& r3,
                                        uint32_t addr) {
    asm volatile("ldmatrix.sync.aligned.m8n8.x4.shared.b16 {%0,%1,%2,%3}, [%4];"
                 : "=r"(r0), "=r"(r1), "=r"(r2), "=r"(r3) : "r"(addr));
}
__device__ __forceinline__ void ldsm_x4t(uint32_t& r0, uint32_t& r1, uint32_t& r2, uint32_t& r3,
                                         uint32_t addr) {
    asm volatile("ldmatrix.sync.aligned.m8n8.x4.trans.shared.b16 {%0,%1,%2,%3}, [%4];"
                 : "=r"(r0), "=r"(r1), "=r"(r2), "=r"(r3) : "r"(addr));
}
__device__ __forceinline__ void mma16816(float* d, const uint32_t* a, const uint32_t* b) {
    asm volatile(
        "mma.sync.aligned.m16n8k16.row.col.f32.f16.f16.f32 "
        "{%0,%1,%2,%3}, {%4,%5,%6,%7}, {%8,%9}, {%0,%1,%2,%3};"
        : "+f"(d[0]), "+f"(d[1]), "+f"(d[2]), "+f"(d[3])
        : "r"(a[0]), "r"(a[1]), "r"(a[2]), "r"(a[3]), "r"(b[0]), "r"(b[1]));
}
__device__ __forceinline__ uint32_t pack_hi(float a, float b) {
    __half2 h = __floats2half2_rn(a, b);
    return *(uint32_t*)&h;
}
__device__ __forceinline__ void cpa16(uint32_t dst, const void* src) {
    asm volatile("cp.async.cg.shared.global [%0], [%1], 16;" :: "r"(dst), "l"(src));
}
#define CP_COMMIT() asm volatile("cp.async.commit_group;" ::: "memory")
#define CP_WAIT1()  asm volatile("cp.async.wait_group 1;" ::: "memory")
#define CP_WAIT0()  asm volatile("cp.async.wait_group 0;" ::: "memory")

// ---------------------------------------------------------------------------
// One-shot conversion kernel: x plain; Wq/Wk rope-pair-permuted; Wv, Wo plain.
// ---------------------------------------------------------------------------
#define XU  (MROWS*DIN/4)
#define WQU (DIN*NH*32)
#define WKU (DIN*NKV*32)
#define WVU (DIN*DKV/4)
#define WOU (DOUT*DOUT/4)
#define CONV_TOTAL (XU + WQU + WKU + WVU + WOU)

__global__ void conv_all(const float* __restrict__ x,
                         const float* __restrict__ Wq, const float* __restrict__ Wk,
                         const float* __restrict__ Wv, const float* __restrict__ Wo,
                         __half* __restrict__ xh, __half* __restrict__ wqkv,
                         __half* __restrict__ woh)
{
    int i = blockIdx.x * blockDim.x + threadIdx.x;
    if (i < XU) {
        float4 f = ((const float4*)x)[i];
        ((uint2*)xh)[i] = make_uint2(pack_hi(f.x, f.y), pack_hi(f.z, f.w));
        return;
    }
    i -= XU;
    if (i < WQU) {      // Wq permuted
        int k = i >> 9, h = (i >> 5) & 15, j2 = i & 31;
        const float* base = Wq + (size_t)k * DOUT + h * HD + j2 * 2;
        float2 a = *(const float2*)base;
        float2 b = *(const float2*)(base + 64);
        *(uint2*)(wqkv + (size_t)k * NQKV + h * HD + j2 * 4)
            = make_uint2(pack_hi(a.x, b.x), pack_hi(a.y, b.y));
        return;
    }
    i -= WQU;
    if (i < WKU) {      // Wk permuted
        int k = i >> 7, h = (i >> 5) & 3, j2 = i & 31;
        const float* base = Wk + (size_t)k * DKV + h * HD + j2 * 2;
        float2 a = *(const float2*)base;
        float2 b = *(const float2*)(base + 64);
        *(uint2*)(wqkv + (size_t)k * NQKV + DOUT + h * HD + j2 * 4)
            = make_uint2(pack_hi(a.x, b.x), pack_hi(a.y, b.y));
        return;
    }
    i -= WKU;
    if (i < WVU) {      // Wv plain
        int k = i >> 7, c4 = i & 127;
        float4 f = *(const float4*)(Wv + (size_t)k * DKV + c4 * 4);
        *(uint2*)(wqkv + (size_t)k * NQKV + DOUT + DKV + c4 * 4)
            = make_uint2(pack_hi(f.x, f.y), pack_hi(f.z, f.w));
        return;
    }
    i -= WVU;
    if (i < WOU) {      // Wo plain (dense)
        float4 f = ((const float4*)Wo)[i];
        ((uint2*)woh)[i] = make_uint2(pack_hi(f.x, f.y), pack_hi(f.z, f.w));
    }
}

// ---------------------------------------------------------------------------
// Shared GEMM mainloop: runtime K/N, chunk loop unrolled x2 (stable, verified)
// ---------------------------------------------------------------------------
#define KC    64
#define A_STR 72
#define B_STR 136
#define A_OFF 0
#define B_OFF 18432
#define STAGE 35840
#define GEMM_SMEM (2*STAGE)

#define GEMM_LOAD(k0, st)                                                            \
    {                                                                                \
        uint32_t base = sb + (st) * STAGE;                                           \
        _Pragma("unroll")                                                            \
        for (int i = 0; i < 4; i++) {                                                \
            int li = t + (i << 8);                                                   \
            int r = li >> 3, ch = li & 7;                                            \
            size_t so = (size_t)(row0 + r) * K + (k0) + ch * 8;                      \
            cpa16(base + A_OFF + (uint32_t)(r * A_STR + ch * 8) * 2, Ah + so);       \
        }                                                                            \
        _Pragma("unroll")                                                            \
        for (int i = 0; i < 4; i++) {                                                \
            int li = t + (i << 8);                                                   \
            int kk = li >> 4, ch = li & 15;                                          \
            size_t so = (size_t)((k0) + kk) * N + col0 + ch * 8;                     \
            cpa16(base + B_OFF + (uint32_t)(kk * B_STR + ch * 8) * 2, Bh + so);      \
        }                                                                            \
    }

#define GEMM_MAINLOOP()                                                              \
    GEMM_LOAD(0, 0);                                                                 \
    CP_COMMIT();                                                                     \
    GEMM_LOAD(KC, 1);                                                                \
    CP_COMMIT();                                                                     \
    _Pragma("unroll 2")                                                              \
    for (int c = 0; c < nch; c++) {                                                  \
        CP_WAIT1();                                                                  \
        __syncthreads();                                                             \
        const uint32_t stb = sb + (c & 1) * STAGE;                                   \
        _Pragma("unroll")                                                            \
        for (int ks = 0; ks < 4; ks++) {                                             \
            uint32_t a[4][4];                                                        \
            _Pragma("unroll")                                                        \
            for (int mi = 0; mi < 4; mi++) {                                         \
                uint32_t ao = (uint32_t)((wm * 64 + mi * 16 + arow) * A_STR          \
                                         + ks * 16 + agrp) * 2;                      \
                ldsm_x4(a[mi][0], a[mi][1], a[mi][2], a[mi][3], stb + A_OFF + ao);   \
            }                                                                        \
            uint32_t b[4][2];                                                        \
            _Pragma("unroll")                                                        \
            for (int p = 0; p < 2; p++) {                                            \
                uint32_t bo = (uint32_t)((ks * 16 + arow) * B_STR                    \
                                         + wn * 32 + p * 16 + agrp) * 2;             \
                uint32_t r0, r1, r2, r3;                                             \
                ldsm_x4t(r0, r1, r2, r3, stb + B_OFF + bo);                          \
                b[2 * p][0] = r0;     b[2 * p][1] = r1;                              \
                b[2 * p + 1][0] = r2; b[2 * p + 1][1] = r3;                          \
            }                                                                        \
            _Pragma("unroll")                                                        \
            for (int mi = 0; mi < 4; mi++)                                           \
                _Pragma("unroll")                                                    \
                for (int nt = 0; nt < 4; nt++)                                       \
                    mma16816(acc[mi][nt], a[mi], b[nt]);                             \
        }                                                                            \
        __syncthreads();                                                             \
        if (c + 2 < nch) GEMM_LOAD((c + 2) * KC, (c & 1));                           \
        CP_COMMIT();                                                                 \
    }

// ---------------------------------------------------------------------------
// QKV GEMM with fused rope/scale/fp16 epilogue (runtime dims).
// ---------------------------------------------------------------------------
__global__ __launch_bounds__(256, 2) void gemm_qkv(
    const __half* __restrict__ Ah, const __half* __restrict__ Bh,
    const float* __restrict__ cosT, const float* __restrict__ sinT,
    __half* __restrict__ Qh, __half* __restrict__ Kh, __half* __restrict__ Vh,
    int M, int N, int K)
{
    extern __shared__ char smg[];
    const uint32_t sb = smem_u32(smg);
    const int t = threadIdx.x;
    const int wid = t >> 5, lane = t & 31;
    const int wm = wid >> 2, wn = wid & 3;
    const int row0 = blockIdx.y << 7, col0 = blockIdx.x << 7;
    const int nch = K / KC;

    float acc[4][4][4];
#pragma unroll
    for (int mi = 0; mi < 4; mi++)
#pragma unroll
        for (int nt = 0; nt < 4; nt++)
#pragma unroll
            for (int e = 0; e < 4; e++) acc[mi][nt][e] = 0.f;

    const int arow = lane & 15, agrp = (lane >> 4) << 3;

    GEMM_MAINLOOP();

    const int drow = lane >> 2, dcol = (lane & 3) * 2;
    const float scale = 0.08838834764831845f * 1.4426950408889634f; // /sqrt(HD) * log2(e)

    if (col0 < DOUT) {
#pragma unroll
        for (int mi = 0; mi < 4; mi++) {
            int r = row0 + wm * 64 + mi * 16 + drow;
            int s0 = r & (Sq - 1), s1 = (r + 8) & (Sq - 1);
#pragma unroll
            for (int nt = 0; nt < 4; nt++) {
                int col = col0 + wn * 32 + nt * 8 + dcol;
                int jj = (col & 127) >> 1;
                float c0 = cosT[s0 * HD + jj], n0 = sinT[s0 * HD + jj];
                float c1 = cosT[s1 * HD + jj], n1 = sinT[s1 * HD + jj];
                float t1 = acc[mi][nt][0], t2 = acc[mi][nt][1];
                uint32_t p0 = pack_hi((t1 * c0 - t2 * n0) * scale,
                                      (t2 * c0 + t1 * n0) * scale);
                t1 = acc[mi][nt][2]; t2 = acc[mi][nt][3];
                uint32_t p1 = pack_hi((t1 * c1 - t2 * n1) * scale,
                                      (t2 * c1 + t1 * n1) * scale);
                *(uint32_t*)(Qh + (size_t)r * DOUT + col)       = p0;
                *(uint32_t*)(Qh + (size_t)(r + 8) * DOUT + col) = p1;
            }
        }
    } else if (col0 < DOUT + DKV) {
#pragma unroll
        for (int mi = 0; mi < 4; mi++) {
            int r = row0 + wm * 64 + mi * 16 + drow;
            int s0 = r & (Sq - 1), s1 = (r + 8) & (Sq - 1);
#pragma unroll
            for (int nt = 0; nt < 4; nt++) {
                int col = col0 + wn * 32 + nt * 8 + dcol;
                int kc = col - DOUT;
                int jj = (kc & 127) >> 1;
                float c0 = cosT[s0 * HD + jj], n0 = sinT[s0 * HD + jj];
                float c1 = cosT[s1 * HD + jj], n1 = sinT[s1 * HD + jj];
                float t1 = acc[mi][nt][0], t2 = acc[mi][nt][1];
                uint32_t p0 = pack_hi(t1 * c0 - t2 * n0, t2 * c0 + t1 * n0);
                t1 = acc[mi][nt][2]; t2 = acc[mi][nt][3];
                uint32_t p1 = pack_hi(t1 * c1 - t2 * n1, t2 * c1 + t1 * n1);
                *(uint32_t*)(Kh + (size_t)r * DKV + kc)       = p0;
                *(uint32_t*)(Kh + (size_t)(r + 8) * DKV + kc) = p1;
            }
        }
    } else {
#pragma unroll
        for (int mi = 0; mi < 4; mi++) {
            int r = row0 + wm * 64 + mi * 16 + drow;
#pragma unroll
            for (int nt = 0; nt < 4; nt++) {
                int col = col0 + wn * 32 + nt * 8 + dcol;
                int vc = col - DOUT - DKV;
                *(uint32_t*)(Vh + (size_t)r * DKV + vc)
                    = pack_hi(acc[mi][nt][0], acc[mi][nt][1]);
                *(uint32_t*)(Vh + (size_t)(r + 8) * DKV + vc)
                    = pack_hi(acc[mi][nt][2], acc[mi][nt][3]);
            }
        }
    }
}

// ---------------------------------------------------------------------------
// Output-projection GEMM (plain fp32 epilogue, runtime dims).
// ---------------------------------------------------------------------------
__global__ __launch_bounds__(256, 2) void gemm_out(
    const __half* __restrict__ Ah, const __half* __restrict__ Bh,
    float* __restrict__ C, int M, int N, int K)
{
    extern __shared__ char smg[];
    const uint32_t sb = smem_u32(smg);
    const int t = threadIdx.x;
    const int wid = t >> 5, lane = t & 31;
    const int wm = wid >> 2, wn = wid & 3;
    const int row0 = blockIdx.y << 7, col0 = blockIdx.x << 7;
    const int nch = K / KC;

    float acc[4][4][4];
#pragma unroll
    for (int mi = 0; mi < 4; mi++)
#pragma unroll
        for (int nt = 0; nt < 4; nt++)
#pragma unroll
            for (int e = 0; e < 4; e++) acc[mi][nt][e] = 0.f;

    const int arow = lane & 15, agrp = (lane >> 4) << 3;

    GEMM_MAINLOOP();

    const int drow = lane >> 2, dcol = (lane & 3) * 2;
#pragma unroll
    for (int mi = 0; mi < 4; mi++) {
        int r = row0 + wm * 64 + mi * 16 + drow;
#pragma unroll
        for (int nt = 0; nt < 4; nt++) {
            int col = col0 + wn * 32 + nt * 8 + dcol;
            *(float2*)(C + (size_t)r * N + col)       = make_float2(acc[mi][nt][0], acc[mi][nt][1]);
            *(float2*)(C + (size_t)(r + 8) * N + col) = make_float2(acc[mi][nt][2], acc[mi][nt][3]);
        }
    }
}

// ---------------------------------------------------------------------------
// Tensor-core flash attention: FBM=64, 128 threads (4 warps x 16 rows),
// 2 CTAs/SM via (128,2) — reg cap is 256 so no spill; per-warp arithmetic
// byte-identical to the verified 256-thread version.
// ---------------------------------------------------------------------------
#define FBM 64
#define FBN 64
#define F_STR 136
#define QH_OFF 0
#define KV0_OFF 17408
#define KV_STAGE 34816
#define FATTN_SMEM 87040

#define KV_LOAD(k0_, st)                                                             \
    {                                                                                \
        const __half* kb = Kh + ((size_t)b * Sq + (k0_)) * DKV + kh * HD;            \
        const __half* vb = Vh + ((size_t)b * Sq + (k0_)) * DKV + kh * HD;            \
        uint32_t kbase = sb + KV0_OFF + (st) * KV_STAGE;                             \
        _Pragma("unroll")                                                            \
        for (int i = 0; i < 8; i++) {                                                \
            int li = t + (i << 7);                                                   \
            int r = li >> 4, c8 = li & 15;                                           \
            uint32_t dof = (uint32_t)(r * F_STR + c8 * 8) * 2;                       \
            cpa16(kbase + dof,         kb + (size_t)r * DKV + c8 * 8);               \
            cpa16(kbase + 17408 + dof, vb + (size_t)r * DKV + c8 * 8);               \
        }                                                                            \
    }

__global__ __launch_bounds__(128, 2) void flash_attn_mma(
    const __half* __restrict__ Qh, const __half* __restrict__ Kh,
    const __half* __restrict__ Vh, __half* __restrict__ Oh)
{
    extern __shared__ char smf[];
    const uint32_t sb = smem_u32(smf);
    const int qtile = gridDim.x - 1 - blockIdx.x;   // big-work blocks first
    const int h = blockIdx.y, b = blockIdx.z;
    const int kh = h >> 2;
    const int t = threadIdx.x;
    const int w = t >> 5, lane = t & 31;
    const int arow = lane & 15, agrp = (lane >> 4) << 3;
    const int q0 = qtile * FBM;

    {
        const __half* qb = Qh + ((size_t)b * Sq + q0) * DOUT + h * HD;
#pragma unroll
        for (int i = 0; i < 4; i++) {
            int li = t + (i << 7);
            int r = li >> 3, c8 = li & 7;
            uint32_t dof = (uint32_t)(r * F_STR + c8 * 16) * 2;
            cpa16(sb + QH_OFF + dof,      qb + (size_t)r * DOUT + c8 * 16);
            cpa16(sb + QH_OFF + dof + 16, qb + (size_t)r * DOUT + c8 * 16 + 8);
        }
    }
    KV_LOAD(0, 0);
    CP_COMMIT();

    float o[16][4];
#pragma unroll
    for (int nt = 0; nt < 16; nt++)
#pragma unroll
        for (int e = 0; e < 4; e++) o[nt][e] = 0.f;
    float m0 = -1e30f, m1 = -1e30f, l0 = 0.f, l1 = 0.f;

    const int wrow_max = q0 + w * 16 + 15;
    const int niter = (q0 + FBM) / FBN;

    for (int it = 0; it < niter; it++) {
        const int k0 = it * FBN;
        if (it + 1 < niter) {
            KV_LOAD((it + 1) * FBN, (it + 1) & 1);
            CP_COMMIT();
            CP_WAIT1();
        } else {
            CP_WAIT0();
        }
        __syncthreads();

        if (k0 <= wrow_max) {
            const uint32_t kvb = sb + KV0_OFF + (it & 1) * KV_STAGE;
            const uint32_t KHo = kvb, VHo = kvb + 17408;

            float s[8][4];
#pragma unroll
            for (int nt = 0; nt < 8; nt++)
#pragma unroll
                for (int e = 0; e < 4; e++) s[nt][e] = 0.f;

#pragma unroll
            for (int ks = 0; ks < 8; ks++) {
                uint32_t q[4];
                uint32_t qa = (uint32_t)((w * 16 + arow) * F_STR + ks * 16 + agrp) * 2;
                ldsm_x4(q[0], q[1], q[2], q[3], sb + QH_OFF + qa);
#pragma unroll
                for (int g = 0; g < 4; g++) {
                    uint32_t ka = (uint32_t)((g * 16 + arow) * F_STR + ks * 16 + agrp) * 2;
                    uint32_t h0, h1, h2, h3;
                    ldsm_x4(h0, h1, h2, h3, KHo + ka);
                    uint32_t b0[2] = {h0, h2}, b1[2] = {h1, h3};
                    mma16816(s[2 * g],     q, b0);
                    mma16816(s[2 * g + 1], q, b1);
                }
            }

            const int rg0 = q0 + w * 16 + (lane >> 2);
            if (k0 + FBN - 1 > q0 + w * 16) {
                int cg = k0 + 2 * (lane & 3);
#pragma unroll
                for (int nt = 0; nt < 8; nt++) {
                    int c = cg + nt * 8;
                    if (c     > rg0)     s[nt][0] = -1e30f;
                    if (c + 1 > rg0)     s[nt][1] = -1e30f;
                    if (c     > rg0 + 8) s[nt][2] = -1e30f;
                    if (c + 1 > rg0 + 8) s[nt][3] = -1e30f;
                }
            }

            float mx0 = -1e30f, mx1 = -1e30f;
#pragma unroll
            for (int nt = 0; nt < 8; nt++) {
                mx0 = fmaxf(mx0, fmaxf(s[nt][0], s[nt][1]));
                mx1 = fmaxf(mx1, fmaxf(s[nt][2], s[nt][3]));
            }
            mx0 = fmaxf(mx0, __shfl_xor_sync(0xffffffffu, mx0, 1));
            mx0 = fmaxf(mx0, __shfl_xor_sync(0xffffffffu, mx0, 2));
            mx1 = fmaxf(mx1, __shfl_xor_sync(0xffffffffu, mx1, 1));
            mx1 = fmaxf(mx1, __shfl_xor_sync(0xffffffffu, mx1, 2));
            float mn0 = fmaxf(m0, mx0), mn1 = fmaxf(m1, mx1);
            float a0 = exp2f(m0 - mn0), a1 = exp2f(m1 - mn1);
            m0 = mn0; m1 = mn1;

            float sum0 = 0.f, sum1 = 0.f;
#pragma unroll
            for (int nt = 0; nt < 8; nt++) {
                s[nt][0] = exp2f(s[nt][0] - mn0);
                s[nt][1] = exp2f(s[nt][1] - mn0);
                s[nt][2] = exp2f(s[nt][2] - mn1);
                s[nt][3] = exp2f(s[nt][3] - mn1);
                sum0 += s[nt][0] + s[nt][1];
                sum1 += s[nt][2] + s[nt][3];
            }
            sum0 += __shfl_xor_sync(0xffffffffu, sum0, 1);
            sum0 += __shfl_xor_sync(0xffffffffu, sum0, 2);
            sum1 += __shfl_xor_sync(0xffffffffu, sum1, 1);
            sum1 += __shfl_xor_sync(0xffffffffu, sum1, 2);
            l0 = l0 * a0 + sum0;
            l1 = l1 * a1 + sum1;

#pragma unroll
            for (int nt = 0; nt < 16; nt++) {
                o[nt][0] *= a0; o[nt][1] *= a0;
                o[nt][2] *= a1; o[nt][3] *= a1;
            }

            uint32_t ap[4][4];
#pragma unroll
            for (int ts = 0; ts < 4; ts++) {
                ap[ts][0] = pack_hi(s[2 * ts][0],     s[2 * ts][1]);
                ap[ts][1] = pack_hi(s[2 * ts][2],     s[2 * ts][3]);
                ap[ts][2] = pack_hi(s[2 * ts + 1][0], s[2 * ts + 1][1]);
                ap[ts][3] = pack_hi(s[2 * ts + 1][2], s[2 * ts + 1][3]);
            }

#pragma unroll
            for (int ts = 0; ts < 4; ts++) {
#pragma unroll
                for (int g = 0; g < 8; g++) {
                    uint32_t va = (uint32_t)((ts * 16 + arow) * F_STR + g * 16 + agrp) * 2;
                    uint32_t h0, h1, h2, h3;
                    ldsm_x4t(h0, h1, h2, h3, VHo + va);
                    uint32_t b0[2] = {h0, h1}, b1[2] = {h2, h3};
                    mma16816(o[2 * g],     ap[ts], b0);
                    mma16816(o[2 * g + 1], ap[ts], b1);
                }
            }
        }
        __syncthreads();
    }

    float inv0 = 1.f / l0, inv1 = 1.f / l1;
    const int rg0 = q0 + w * 16 + (lane >> 2);
    size_t base0 = ((size_t)b * Sq + rg0) * DOUT + h * HD + 2 * (lane & 3);
    size_t base1 = base0 + (size_t)8 * DOUT;
#pragma unroll
    for (int nt = 0; nt < 16; nt++) {
        ((uint32_t*)Oh)[(base0 + nt * 8) >> 1] = pack_hi(o[nt][0] * inv0, o[nt][1] * inv0);
        ((uint32_t*)Oh)[(base1 + nt * 8) >> 1] = pack_hi(o[nt][2] * inv1, o[nt][3] * inv1);
    }
}

// ---------------------------------------------------------------------------
extern "C" void kernel_launch(void* const* d_in, const int* in_sizes, int n_in,
                              void* d_out, int out_size)
{
    const float* x    = (const float*)d_in[0];
    const float* Wq   = (const float*)d_in[1];
    const float* Wk   = (const float*)d_in[2];
    const float* Wv   = (const float*)d_in[3];
    const float* Wo   = (const float*)d_in[4];
    const float* cosT = (const float*)d_in[5];
    const float* sinT = (const float*)d_in[6];
    float* out = (float*)d_out;

    __half *xh, *wqkv, *woh, *qh, *khb, *vhb, *ch;
    cudaGetSymbolAddress((void**)&xh,   g_xh);
    cudaGetSymbolAddress((void**)&wqkv, g_wqkv);
    cudaGetSymbolAddress((void**)&woh,  g_woh);
    cudaGetSymbolAddress((void**)&qh,   g_qh);
    cudaGetSymbolAddress((void**)&khb,  g_kh);
    cudaGetSymbolAddress((void**)&vhb,  g_vh);
    cudaGetSymbolAddress((void**)&ch,   g_ch);

    cudaFuncSetAttribute(gemm_qkv,       cudaFuncAttributeMaxDynamicSharedMemorySize, GEMM_SMEM);
    cudaFuncSetAttribute(gemm_out,       cudaFuncAttributeMaxDynamicSharedMemorySize, GEMM_SMEM);
    cudaFuncSetAttribute(flash_attn_mma, cudaFuncAttributeMaxDynamicSharedMemorySize, FATTN_SMEM);

    // One-shot conversion (x + permuted Wq/Wk + Wv + Wo)
    conv_all<<<(CONV_TOTAL + 255) / 256, 256>>>(x, Wq, Wk, Wv, Wo, xh, wqkv, woh);

    // Fused QKV projection + rope + scale(log2e) + fp16
    gemm_qkv<<<dim3(NQKV / 128, MROWS / 128), 256, GEMM_SMEM>>>(
        xh, wqkv, cosT, sinT, qh, khb, vhb, MROWS, NQKV, DIN);

    // Attention (base-2 softmax, FBM=64, 128 thr, 2 CTAs/SM) -> fp16 ctx
    flash_attn_mma<<<dim3(Sq / FBM, NH, Bb), 128, FATTN_SMEM>>>(qh, khb, vhb, ch);

    // Output projection
    gemm_out<<<dim3(DOUT / 128, MROWS / 128), 256, GEMM_SMEM>>>(ch, woh, out, MROWS, DOUT, DOUT);
}